// round 13
// baseline (speedup 1.0000x reference)
#include <cuda_runtime.h>
#include <cuda_fp16.h>
#include <cstdint>

#define NN 65536
#define DD 256
#define KK 2048
#define ZQ (NN*DD)
#define CAP 24

// ---------------------------------------------------------------------------
// device scratch
// ---------------------------------------------------------------------------
__device__ uint4    g_e8[16 * 2048];       // 512KB: [chunk 16][kw 64][code 128] int8x4
__device__ float    g_se[KK];              // per-code int8 scale
__device__ float    g_sume[KK];            // exact sequential sum(e^2)
__device__ float    g_SEmax;               // max_j sum|e_j| (with slack)
__device__ float    g_SEscale;             // max_j s_e (with slack)
__device__ uint4    g_dh[(size_t)NN * 256]; // 256MB fp16 score dump (8 scores/uint4)
__device__ int      g_cand[NN * CAP];
__device__ int      g_cnt[NN];
__device__ int      g_idx[NN];
__device__ double   g_loss;

// ---------------------------------------------------------------------------
// helpers
// ---------------------------------------------------------------------------
__device__ __forceinline__ unsigned encf(float f) {
    unsigned u = __float_as_uint(f);
    return (u & 0x80000000u) ? ~u : (u | 0x80000000u);
}
__device__ __forceinline__ float decf(unsigned k) {
    return (k & 0x80000000u) ? __uint_as_float(k ^ 0x80000000u)
                             : __uint_as_float(~k);
}
__device__ __forceinline__ void cpasync16(void* sdst, const void* gsrc) {
    unsigned s = (unsigned)__cvta_generic_to_shared(sdst);
    asm volatile("cp.async.cg.shared.global [%0], [%1], 16;" :: "r"(s), "l"(gsrc));
}
__device__ __forceinline__ void atomicMaxF(float* addr, float v) {
    atomicMax(reinterpret_cast<int*>(addr), __float_as_int(v));  // v >= 0
}
__device__ __forceinline__ uint32_t pkh(float a, float b) {
    __half2 h = __floats2half2_rn(a, b);
    return *reinterpret_cast<uint32_t*>(&h);
}
__device__ __forceinline__ float2 uph(uint32_t u) {
    __half2 h = *reinterpret_cast<__half2*>(&u);
    return __half22float2(h);
}

// ---------------------------------------------------------------------------
__global__ void init_kernel() { g_SEmax = 0.f; g_SEscale = 0.f; g_loss = 0.0; }

// ---------------------------------------------------------------------------
// prep_e8: per-code int8 quant + exact sume + bound scalars (proven)
// ---------------------------------------------------------------------------
__global__ void prep_e8(const float* __restrict__ emb) {
    const int j = blockIdx.x * 256 + threadIdx.x;   // 2048
    const float* e = emb + (size_t)j * DD;

    float s = 0.f;
    for (int c = 0; c < DD; ++c) {
        float v = e[c];
        s = __fadd_rn(s, __fmul_rn(v, v));
    }
    g_sume[j] = s;

    float mx = 0.f, sa = 0.f;
    for (int c = 0; c < DD; ++c) {
        float a = fabsf(e[c]);
        mx = fmaxf(mx, a);
        sa += a;
    }
    const float mxs = fmaxf(mx, 1e-30f);
    const float se  = mxs / 127.f;
    const float inv = 127.f / mxs;
    g_se[j] = se;
    atomicMaxF(&g_SEmax, sa * 1.0005f);
    atomicMaxF(&g_SEscale, se * 1.0005f);

    const int chunk = j >> 7, code = j & 127;
    uint32_t* dst = reinterpret_cast<uint32_t*>(g_e8) + (size_t)chunk * 8192 + code;
    for (int kw = 0; kw < 64; ++kw) {
        int q0 = max(-127, min(127, __float2int_rn(e[kw * 4 + 0] * inv)));
        int q1 = max(-127, min(127, __float2int_rn(e[kw * 4 + 1] * inv)));
        int q2 = max(-127, min(127, __float2int_rn(e[kw * 4 + 2] * inv)));
        int q3 = max(-127, min(127, __float2int_rn(e[kw * 4 + 3] * inv)));
        dst[kw * 128] = (uint32_t)(q0 & 0xFF) | ((uint32_t)(q1 & 0xFF) << 8)
                      | ((uint32_t)(q2 & 0xFF) << 16) | ((uint32_t)(q3 & 0xFF) << 24);
    }
}

// ---------------------------------------------------------------------------
// assign_dp4a: 64 pixels x 2048 codes per CTA (grid = 1024); z quantized
// in-kernel to int8 (per-pixel scale); e chunks double-buffered; dp4a GEMM;
// scores dumped fp16 to g_dh; per-pixel FINAL min kept in registers/smem;
// tight-window candidate collection fused at the end (re-read from L2).
// smem: Z8 16K | E8 2x32K | m2 1K | sa2 1K | sps 256 | eps 256 |
//       minU 256 | cnt 256 | cand 6144   = 91392
// ---------------------------------------------------------------------------
#define OFF_Z    0
#define OFF_E    16384
#define OFF_M2   81920
#define OFF_SA2  82944
#define OFF_SPS  83968
#define OFF_EPS  84224
#define OFF_MIN  84480
#define OFF_CNT  84736
#define OFF_CAND 84992
#define ASMEM    91136

__global__ void __launch_bounds__(256, 2) assign_dp4a(const float* __restrict__ z) {
    extern __shared__ char sm[];
    uint32_t* Z    = reinterpret_cast<uint32_t*>(sm + OFF_Z);
    uint32_t* E    = reinterpret_cast<uint32_t*>(sm + OFF_E);
    float*    m2   = reinterpret_cast<float*>(sm + OFF_M2);
    float*    sa2  = reinterpret_cast<float*>(sm + OFF_SA2);
    float*    sps  = reinterpret_cast<float*>(sm + OFF_SPS);
    float*    epss = reinterpret_cast<float*>(sm + OFF_EPS);
    unsigned* minU = reinterpret_cast<unsigned*>(sm + OFF_MIN);
    int*      cnt  = reinterpret_cast<int*>(sm + OFF_CNT);
    int*      cand = reinterpret_cast<int*>(sm + OFF_CAND);

    const int tid = threadIdx.x;
    const int tx = tid & 15, ty = tid >> 4;   // tx: 8 codes, ty: 4 pixels
    const int w = tid >> 5, lane = tid & 31;
    const int blk = blockIdx.x;               // 1024 (64 pixels each)
    const int b = blk >> 4, px0 = (blk & 15) << 6;
    const float* zb = z + ((size_t)b << 18) + px0;
    const int px = tid & 63, seg = tid >> 6;  // 4 segs x 64 dims

    // E chunk 0 prefetch (overlaps the z-quant pass)
    {
        const char* es = reinterpret_cast<const char*>(g_e8);
        #pragma unroll
        for (int i = 0; i < 8; ++i) {
            const int t = tid + i * 256;
            cpasync16(sm + OFF_E + t * 16, es + (size_t)t * 16);
        }
    }
    asm volatile("cp.async.commit_group;" ::: "memory");

    if (tid < 64) { minU[tid] = 0xFFFFFFFFu; cnt[tid] = 0; }

    // ---- pass 1: per-pixel maxabs + sum|z| ----
    {
        float mx = 0.f, sa = 0.f;
        #pragma unroll 8
        for (int i = 0; i < 64; ++i) {
            float v = __ldg(&zb[((size_t)(seg * 64 + i) << 10) + px]);
            float a = fabsf(v);
            mx = fmaxf(mx, a);
            sa += a;
        }
        m2[tid] = mx; sa2[tid] = sa;
    }
    __syncthreads();
    if (tid < 64) {
        float mx = fmaxf(fmaxf(m2[tid], m2[tid + 64]),
                         fmaxf(m2[tid + 128], m2[tid + 192]));
        float sa = sa2[tid] + sa2[tid + 64] + sa2[tid + 128] + sa2[tid + 192];
        const float mxs = fmaxf(mx, 1e-30f);
        const float sz = mxs / 127.f;
        sps[tid] = sz;
        m2[tid]  = 127.f / mxs;   // reuse as inv
        // tight window = 2B + fp32 slack + fp16 dump slack
        const float B = 0.5f * sz * g_SEmax
                      + 0.5f * g_SEscale * (sa * 1.0005f + 128.f * sz);
        epss[tid] = 2.f * B + 1e-4f + 4e-4f;
    }
    __syncthreads();

    // ---- pass 2: quantize z -> Z8 [kw][px] ----
    {
        const float inv = m2[px];
        for (int kw = seg * 16; kw < seg * 16 + 16; ++kw) {
            const int c0 = kw * 4;
            int q0 = max(-127, min(127, __float2int_rn(__ldg(&zb[((size_t)(c0 + 0) << 10) + px]) * inv)));
            int q1 = max(-127, min(127, __float2int_rn(__ldg(&zb[((size_t)(c0 + 1) << 10) + px]) * inv)));
            int q2 = max(-127, min(127, __float2int_rn(__ldg(&zb[((size_t)(c0 + 2) << 10) + px]) * inv)));
            int q3 = max(-127, min(127, __float2int_rn(__ldg(&zb[((size_t)(c0 + 3) << 10) + px]) * inv)));
            Z[(kw << 6) + px] = (uint32_t)(q0 & 0xFF) | ((uint32_t)(q1 & 0xFF) << 8)
                              | ((uint32_t)(q2 & 0xFF) << 16) | ((uint32_t)(q3 & 0xFF) << 24);
        }
    }
    asm volatile("cp.async.wait_group 0;" ::: "memory");
    __syncthreads();

    float szp[4], rmin[4];
    #pragma unroll
    for (int pi = 0; pi < 4; ++pi) {
        szp[pi]  = sps[(ty << 2) + pi];
        rmin[pi] = __int_as_float(0x7f800000);
    }

    for (int ci = 0; ci < 16; ++ci) {
        if (ci + 1 < 16) {
            const char* es = reinterpret_cast<const char*>(g_e8) + (size_t)(ci + 1) * 32768;
            char* dst = sm + OFF_E + ((ci + 1) & 1) * 32768;
            #pragma unroll
            for (int i = 0; i < 8; ++i) {
                const int t = tid + i * 256;
                cpasync16(dst + t * 16, es + (size_t)t * 16);
            }
        }
        asm volatile("cp.async.commit_group;" ::: "memory");

        const uint32_t* Bp = E + (ci & 1) * 8192;
        int acc[32];
        #pragma unroll
        for (int i = 0; i < 32; ++i) acc[i] = 0;

        #pragma unroll 8
        for (int kw = 0; kw < 64; ++kw) {
            int4 a  = *reinterpret_cast<const int4*>(Z + (kw << 6) + (ty << 2));
            int4 b0 = *reinterpret_cast<const int4*>(Bp + (kw << 7) + (tx << 3));
            int4 b1 = *reinterpret_cast<const int4*>(Bp + (kw << 7) + (tx << 3) + 4);
            const int aa[4] = {a.x, a.y, a.z, a.w};
            const int bb[8] = {b0.x, b0.y, b0.z, b0.w, b1.x, b1.y, b1.z, b1.w};
            #pragma unroll
            for (int pi = 0; pi < 4; ++pi)
                #pragma unroll
                for (int cj = 0; cj < 8; ++cj)
                    acc[pi * 8 + cj] = __dp4a(aa[pi], bb[cj], acc[pi * 8 + cj]);
        }

        // epilogue: d = sume_j - 2*sz_p*se_j*acc ; track min; dump fp16
        const int jc = ci << 7;
        float q8[8], se8[8];
        #pragma unroll
        for (int cj = 0; cj < 8; ++cj) {
            const int j = jc + (tx << 3) + cj;
            se8[cj] = __ldg(&g_sume[j]);
            q8[cj]  = -2.f * __ldg(&g_se[j]);
        }
        #pragma unroll
        for (int pi = 0; pi < 4; ++pi) {
            const int n = blk * 64 + (ty << 2) + pi;
            float d0 = fmaf((float)acc[pi * 8 + 0] * q8[0], szp[pi], se8[0]);
            float d1 = fmaf((float)acc[pi * 8 + 1] * q8[1], szp[pi], se8[1]);
            float d2 = fmaf((float)acc[pi * 8 + 2] * q8[2], szp[pi], se8[2]);
            float d3 = fmaf((float)acc[pi * 8 + 3] * q8[3], szp[pi], se8[3]);
            float d4 = fmaf((float)acc[pi * 8 + 4] * q8[4], szp[pi], se8[4]);
            float d5 = fmaf((float)acc[pi * 8 + 5] * q8[5], szp[pi], se8[5]);
            float d6 = fmaf((float)acc[pi * 8 + 6] * q8[6], szp[pi], se8[6]);
            float d7 = fmaf((float)acc[pi * 8 + 7] * q8[7], szp[pi], se8[7]);
            rmin[pi] = fminf(rmin[pi], fminf(fminf(fminf(d0, d1), fminf(d2, d3)),
                                             fminf(fminf(d4, d5), fminf(d6, d7))));
            uint4 v;
            v.x = pkh(d0, d1); v.y = pkh(d2, d3);
            v.z = pkh(d4, d5); v.w = pkh(d6, d7);
            g_dh[(size_t)n * 256 + (ci << 4) + tx] = v;
        }

        asm volatile("cp.async.wait_group 0;" ::: "memory");
        __syncthreads();
    }

    // ---- final per-pixel min -> smem ----
    #pragma unroll
    for (int pi = 0; pi < 4; ++pi)
        atomicMin(&minU[(ty << 2) + pi], encf(rmin[pi]));
    __syncthreads();

    // ---- fused collect: warp w handles pixels w*8 .. w*8+7 (L2-hot re-read)
    for (int pp = 0; pp < 8; ++pp) {
        const int p = w * 8 + pp;
        const float thr = decf(minU[p]) + epss[p];
        const uint4* dp = g_dh + (size_t)(blk * 64 + p) * 256;
        #pragma unroll
        for (int i = 0; i < 8; ++i) {
            uint4 v = dp[i * 32 + lane];
            const int j0 = (i * 32 + lane) * 8;
            float2 f0 = uph(v.x), f1 = uph(v.y), f2 = uph(v.z), f3 = uph(v.w);
            if (f0.x <= thr) { int ix = atomicAdd(&cnt[p], 1); if (ix < CAP) cand[p * CAP + ix] = j0; }
            if (f0.y <= thr) { int ix = atomicAdd(&cnt[p], 1); if (ix < CAP) cand[p * CAP + ix] = j0 + 1; }
            if (f1.x <= thr) { int ix = atomicAdd(&cnt[p], 1); if (ix < CAP) cand[p * CAP + ix] = j0 + 2; }
            if (f1.y <= thr) { int ix = atomicAdd(&cnt[p], 1); if (ix < CAP) cand[p * CAP + ix] = j0 + 3; }
            if (f2.x <= thr) { int ix = atomicAdd(&cnt[p], 1); if (ix < CAP) cand[p * CAP + ix] = j0 + 4; }
            if (f2.y <= thr) { int ix = atomicAdd(&cnt[p], 1); if (ix < CAP) cand[p * CAP + ix] = j0 + 5; }
            if (f3.x <= thr) { int ix = atomicAdd(&cnt[p], 1); if (ix < CAP) cand[p * CAP + ix] = j0 + 6; }
            if (f3.y <= thr) { int ix = atomicAdd(&cnt[p], 1); if (ix < CAP) cand[p * CAP + ix] = j0 + 7; }
        }
    }
    __syncthreads();

    if (tid < 64) {
        const int n = blk * 64 + tid;
        int c = cnt[tid];
        g_cnt[n] = c;
        if (c > CAP) c = CAP;
        for (int i = 0; i < c; ++i) g_cand[(size_t)n * CAP + i] = cand[tid * CAP + i];
    }
}

// ---------------------------------------------------------------------------
// refine: exact reference arithmetic on candidates -> g_idx
// ---------------------------------------------------------------------------
__device__ __forceinline__ void dot8(const float* __restrict__ z,
                                     const float* __restrict__ emb,
                                     size_t zbase, const int* ids,
                                     float* m, float& sz, bool do_sz) {
    #pragma unroll
    for (int i = 0; i < 8; ++i) m[i] = 0.f;
    for (int kc = 0; kc < 4; ++kc) {
        float zc[64];
        #pragma unroll
        for (int i = 0; i < 64; ++i)
            zc[i] = __ldg(&z[zbase + ((size_t)(kc * 64 + i) << 10)]);
        if (do_sz)
            #pragma unroll
            for (int i = 0; i < 64; ++i)
                sz = __fadd_rn(sz, __fmul_rn(zc[i], zc[i]));
        #pragma unroll
        for (int cd = 0; cd < 8; ++cd) {
            const float4* ep = reinterpret_cast<const float4*>(
                emb + (size_t)ids[cd] * DD + kc * 64);
            float mm = m[cd];
            #pragma unroll
            for (int q = 0; q < 16; ++q) {
                float4 e = __ldg(&ep[q]);
                mm = fmaf(zc[q * 4 + 0], e.x, mm);
                mm = fmaf(zc[q * 4 + 1], e.y, mm);
                mm = fmaf(zc[q * 4 + 2], e.z, mm);
                mm = fmaf(zc[q * 4 + 3], e.w, mm);
            }
            m[cd] = mm;
        }
    }
}

__global__ void __launch_bounds__(256) refine_kernel(const float* __restrict__ z,
                                                     const float* __restrict__ emb) {
    const int n = blockIdx.x * 256 + threadIdx.x;
    const int b = n >> 10, pix = n & 1023;
    const size_t zbase = ((size_t)b << 18) + pix;
    const int cnt = g_cnt[n];
    float best = __int_as_float(0x7f800000);
    int   bi = 0x7fffffff;
    float sz = 0.f;
    float m[8];
    int ids[8];

    if (cnt <= CAP) {
        for (int g0 = 0; g0 < cnt; g0 += 8) {
            #pragma unroll
            for (int i = 0; i < 8; ++i) {
                int q = g0 + i; if (q >= cnt) q = cnt - 1;
                ids[i] = g_cand[(size_t)n * CAP + q];
            }
            dot8(z, emb, zbase, ids, m, sz, g0 == 0);
            #pragma unroll
            for (int cd = 0; cd < 8; ++cd) {
                if (g0 + cd < cnt) {
                    int j = ids[cd];
                    float d = fmaf(m[cd], -2.f, __fadd_rn(sz, __ldg(&g_sume[j])));
                    if (d < best || (d == best && j < bi)) { best = d; bi = j; }
                }
            }
        }
    } else {
        for (int g0 = 0; g0 < KK; g0 += 8) {
            #pragma unroll
            for (int i = 0; i < 8; ++i) ids[i] = g0 + i;
            dot8(z, emb, zbase, ids, m, sz, g0 == 0);
            #pragma unroll
            for (int cd = 0; cd < 8; ++cd) {
                int j = g0 + cd;
                float d = fmaf(m[cd], -2.f, __fadd_rn(sz, __ldg(&g_sume[j])));
                if (d < best || (d == best && j < bi)) { best = d; bi = j; }
            }
        }
    }
    g_idx[n] = bi;
}

// ---------------------------------------------------------------------------
// quant: R1 version (measured 78us): gather + straight-through + loss
// ---------------------------------------------------------------------------
__global__ void __launch_bounds__(256)
quant_kernel(const float* __restrict__ z, const float* __restrict__ emb,
             float* __restrict__ out) {
    const size_t i = ((size_t)blockIdx.x * 256 + threadIdx.x) * 4;
    const int c = (int)((i >> 10) & 255);
    const int n = (int)(((i >> 18) << 10) | (i & 1023));

    int4   id4 = *reinterpret_cast<const int4*>(&g_idx[n]);
    float4 zp  = *reinterpret_cast<const float4*>(&z[i]);

    float e0 = __ldg(&emb[(size_t)id4.x * DD + c]);
    float e1 = __ldg(&emb[(size_t)id4.y * DD + c]);
    float e2 = __ldg(&emb[(size_t)id4.z * DD + c]);
    float e3 = __ldg(&emb[(size_t)id4.w * DD + c]);

    float t0 = __fsub_rn(e0, zp.x);
    float t1 = __fsub_rn(e1, zp.y);
    float t2 = __fsub_rn(e2, zp.z);
    float t3 = __fsub_rn(e3, zp.w);

    float4 o;
    o.x = __fadd_rn(zp.x, t0);
    o.y = __fadd_rn(zp.y, t1);
    o.z = __fadd_rn(zp.z, t2);
    o.w = __fadd_rn(zp.w, t3);
    *reinterpret_cast<float4*>(&out[i]) = o;

    double s = (double)__fmul_rn(t0, t0) + (double)__fmul_rn(t1, t1)
             + (double)__fmul_rn(t2, t2) + (double)__fmul_rn(t3, t3);

    #pragma unroll
    for (int off = 16; off; off >>= 1)
        s += __shfl_down_sync(0xffffffffu, s, off);
    __shared__ double ws[8];
    const int warp = threadIdx.x >> 5, lane = threadIdx.x & 31;
    if (lane == 0) ws[warp] = s;
    __syncthreads();
    if (threadIdx.x == 0) {
        double t = 0.0;
        #pragma unroll
        for (int w = 0; w < 8; ++w) t += ws[w];
        atomicAdd(&g_loss, t);
    }
}

// ---------------------------------------------------------------------------
__global__ void write_extras_kernel(float* __restrict__ out, int out_size) {
    const int t = blockIdx.x * 256 + threadIdx.x;
    if (out_size == NN) { if (t < NN) out[t] = (float)g_idx[t]; return; }
    const int rem = out_size - ZQ;
    if (rem >= NN && t < NN) out[ZQ + t] = (float)g_idx[t];
    if (rem >= NN + 1 && t == 0) {
        float m = (float)(g_loss * (1.0 / 16777216.0));
        out[ZQ + NN] = __fadd_rn(m, __fmul_rn(0.25f, m));
    }
    if (rem >= 2 * NN + 1 && t < NN) out[ZQ + NN + 1 + t] = (float)g_idx[t];
}

// ---------------------------------------------------------------------------
extern "C" void kernel_launch(void* const* d_in, const int* in_sizes, int n_in,
                              void* d_out, int out_size) {
    const float* z;
    const float* emb;
    if (in_sizes[0] == ZQ) { z = (const float*)d_in[0]; emb = (const float*)d_in[1]; }
    else                   { z = (const float*)d_in[1]; emb = (const float*)d_in[0]; }
    float* out = (float*)d_out;

    cudaFuncSetAttribute(assign_dp4a,
                         cudaFuncAttributeMaxDynamicSharedMemorySize, ASMEM);

    init_kernel<<<1, 1>>>();
    prep_e8<<<8, 256>>>(emb);
    assign_dp4a<<<1024, 256, ASMEM>>>(z);
    refine_kernel<<<256, 256>>>(z, emb);
    if (out_size >= ZQ)
        quant_kernel<<<(NN * DD) / (256 * 4), 256>>>(z, emb, out);
    if (out_size > ZQ || out_size == NN)
        write_extras_kernel<<<NN / 256, 256>>>(out, out_size);
}

// round 14
// speedup vs baseline: 2.4057x; 2.4057x over previous
#include <cuda_runtime.h>
#include <cstdint>

#define NN 65536
#define DD 256
#define KK 2048
#define ZQ (NN*DD)
#define CAP 32

// ---------------------------------------------------------------------------
// device scratch
// ---------------------------------------------------------------------------
__device__ uint4    g_e8[16 * 2048];       // 512KB: [chunk 16][kw 64][code 128] int8x4
__device__ float    g_se[KK];              // per-code int8 scale
__device__ float    g_sume[KK];            // exact sequential sum(e^2)
__device__ float    g_SEmax;               // max_j sum|e_j| (with slack)
__device__ float    g_SEscale;             // max_j s_e (with slack)
__device__ uint4    g_db[(size_t)NN * 256]; // 256MB bf16 score dump (8 scores/uint4)
__device__ float    g_eps[NN];             // per-pixel tight window
__device__ int      g_cand[NN * CAP];
__device__ int      g_cnt[NN];
__device__ int      g_idx[NN];
__device__ double   g_loss;

// ---------------------------------------------------------------------------
// helpers
// ---------------------------------------------------------------------------
__device__ __forceinline__ void cpasync16(void* sdst, const void* gsrc) {
    unsigned s = (unsigned)__cvta_generic_to_shared(sdst);
    asm volatile("cp.async.cg.shared.global [%0], [%1], 16;" :: "r"(s), "l"(gsrc));
}
__device__ __forceinline__ void atomicMaxF(float* addr, float v) {
    atomicMax(reinterpret_cast<int*>(addr), __float_as_int(v));  // v >= 0
}
// bf16 pack/unpack via integer ops (round-to-nearest-even), no half intrinsics
__device__ __forceinline__ uint32_t pkbf(float a, float b) {
    uint32_t ua = __float_as_uint(a);
    ua = (ua + 0x7fffu + ((ua >> 16) & 1u)) >> 16;
    uint32_t ub = __float_as_uint(b);
    ub = (ub + 0x7fffu + ((ub >> 16) & 1u)) >> 16;
    return ua | (ub << 16);
}
__device__ __forceinline__ float lo_bf(uint32_t v) { return __uint_as_float(v << 16); }
__device__ __forceinline__ float hi_bf(uint32_t v) { return __uint_as_float(v & 0xffff0000u); }

// ---------------------------------------------------------------------------
__global__ void init_kernel() { g_SEmax = 0.f; g_SEscale = 0.f; g_loss = 0.0; }

// ---------------------------------------------------------------------------
// prep_e8: per-code int8 quant + exact sume + bound scalars (proven)
// ---------------------------------------------------------------------------
__global__ void prep_e8(const float* __restrict__ emb) {
    const int j = blockIdx.x * 256 + threadIdx.x;   // 2048
    const float* e = emb + (size_t)j * DD;

    float s = 0.f;
    for (int c = 0; c < DD; ++c) {
        float v = e[c];
        s = __fadd_rn(s, __fmul_rn(v, v));
    }
    g_sume[j] = s;

    float mx = 0.f, sa = 0.f;
    for (int c = 0; c < DD; ++c) {
        float a = fabsf(e[c]);
        mx = fmaxf(mx, a);
        sa += a;
    }
    const float mxs = fmaxf(mx, 1e-30f);
    const float se  = mxs / 127.f;
    const float inv = 127.f / mxs;
    g_se[j] = se;
    atomicMaxF(&g_SEmax, sa * 1.0005f);
    atomicMaxF(&g_SEscale, se * 1.0005f);

    const int chunk = j >> 7, code = j & 127;
    uint32_t* dst = reinterpret_cast<uint32_t*>(g_e8) + (size_t)chunk * 8192 + code;
    for (int kw = 0; kw < 64; ++kw) {
        int q0 = max(-127, min(127, __float2int_rn(e[kw * 4 + 0] * inv)));
        int q1 = max(-127, min(127, __float2int_rn(e[kw * 4 + 1] * inv)));
        int q2 = max(-127, min(127, __float2int_rn(e[kw * 4 + 2] * inv)));
        int q3 = max(-127, min(127, __float2int_rn(e[kw * 4 + 3] * inv)));
        dst[kw * 128] = (uint32_t)(q0 & 0xFF) | ((uint32_t)(q1 & 0xFF) << 8)
                      | ((uint32_t)(q2 & 0xFF) << 16) | ((uint32_t)(q3 & 0xFF) << 24);
    }
}

// ---------------------------------------------------------------------------
// assign_dp4a: 64 pixels x 2048 codes per CTA (grid = 1024); z quantized
// in-kernel to int8 (per-pixel scale); e chunks double-buffered; dp4a GEMM;
// ALL scores dumped (bf16-packed) to g_db; selection in collect_kernel.
// smem: Z8 16K | E8 2x32K | m2 1K | sa2 1K | sps 256 | eps 256  = 84480
// ---------------------------------------------------------------------------
#define OFF_Z    0
#define OFF_E    16384
#define OFF_M2   81920
#define OFF_SA2  82944
#define OFF_SPS  83968
#define OFF_EPS  84224
#define ASMEM    84480

__global__ void __launch_bounds__(256, 2) assign_dp4a(const float* __restrict__ z) {
    extern __shared__ char sm[];
    uint32_t* Z    = reinterpret_cast<uint32_t*>(sm + OFF_Z);
    uint32_t* E    = reinterpret_cast<uint32_t*>(sm + OFF_E);
    float*    m2   = reinterpret_cast<float*>(sm + OFF_M2);
    float*    sa2  = reinterpret_cast<float*>(sm + OFF_SA2);
    float*    sps  = reinterpret_cast<float*>(sm + OFF_SPS);
    float*    epss = reinterpret_cast<float*>(sm + OFF_EPS);

    const int tid = threadIdx.x;
    const int tx = tid & 15, ty = tid >> 4;   // tx: 8 codes, ty: 4 pixels
    const int blk = blockIdx.x;               // 1024 (64 pixels each)
    const int b = blk >> 4, px0 = (blk & 15) << 6;
    const float* zb = z + ((size_t)b << 18) + px0;
    const int px = tid & 63, seg = tid >> 6;  // 4 segs x 64 dims

    // E chunk 0 prefetch (overlaps the z-quant pass)
    {
        const char* es = reinterpret_cast<const char*>(g_e8);
        #pragma unroll
        for (int i = 0; i < 8; ++i) {
            const int t = tid + i * 256;
            cpasync16(sm + OFF_E + t * 16, es + (size_t)t * 16);
        }
    }
    asm volatile("cp.async.commit_group;" ::: "memory");

    // ---- pass 1: per-pixel maxabs + sum|z| ----
    {
        float mx = 0.f, sa = 0.f;
        #pragma unroll 8
        for (int i = 0; i < 64; ++i) {
            float v = __ldg(&zb[((size_t)(seg * 64 + i) << 10) + px]);
            float a = fabsf(v);
            mx = fmaxf(mx, a);
            sa += a;
        }
        m2[tid] = mx; sa2[tid] = sa;
    }
    __syncthreads();
    if (tid < 64) {
        float mx = fmaxf(fmaxf(m2[tid], m2[tid + 64]),
                         fmaxf(m2[tid + 128], m2[tid + 192]));
        float sa = sa2[tid] + sa2[tid + 64] + sa2[tid + 128] + sa2[tid + 192];
        const float mxs = fmaxf(mx, 1e-30f);
        const float sz = mxs / 127.f;
        sps[tid] = sz;
        m2[tid]  = 127.f / mxs;   // reuse as inv
        // window = 2B + fp32 slack + bf16 dump slack (2 * 1.2e-4)
        const float B = 0.5f * sz * g_SEmax
                      + 0.5f * g_SEscale * (sa * 1.0005f + 128.f * sz);
        const float eps = 2.f * B + 1e-4f + 2.4e-4f;
        epss[tid] = eps;
        g_eps[blk * 64 + tid] = eps;
    }
    __syncthreads();

    // ---- pass 2: quantize z -> Z8 [kw][px] ----
    {
        const float inv = m2[px];
        for (int kw = seg * 16; kw < seg * 16 + 16; ++kw) {
            const int c0 = kw * 4;
            int q0 = max(-127, min(127, __float2int_rn(__ldg(&zb[((size_t)(c0 + 0) << 10) + px]) * inv)));
            int q1 = max(-127, min(127, __float2int_rn(__ldg(&zb[((size_t)(c0 + 1) << 10) + px]) * inv)));
            int q2 = max(-127, min(127, __float2int_rn(__ldg(&zb[((size_t)(c0 + 2) << 10) + px]) * inv)));
            int q3 = max(-127, min(127, __float2int_rn(__ldg(&zb[((size_t)(c0 + 3) << 10) + px]) * inv)));
            Z[(kw << 6) + px] = (uint32_t)(q0 & 0xFF) | ((uint32_t)(q1 & 0xFF) << 8)
                              | ((uint32_t)(q2 & 0xFF) << 16) | ((uint32_t)(q3 & 0xFF) << 24);
        }
    }
    asm volatile("cp.async.wait_group 0;" ::: "memory");
    __syncthreads();

    float szp[4];
    #pragma unroll
    for (int pi = 0; pi < 4; ++pi) szp[pi] = sps[(ty << 2) + pi];

    for (int ci = 0; ci < 16; ++ci) {
        if (ci + 1 < 16) {
            const char* es = reinterpret_cast<const char*>(g_e8) + (size_t)(ci + 1) * 32768;
            char* dst = sm + OFF_E + ((ci + 1) & 1) * 32768;
            #pragma unroll
            for (int i = 0; i < 8; ++i) {
                const int t = tid + i * 256;
                cpasync16(dst + t * 16, es + (size_t)t * 16);
            }
        }
        asm volatile("cp.async.commit_group;" ::: "memory");

        const uint32_t* Bp = E + (ci & 1) * 8192;
        int acc[32];
        #pragma unroll
        for (int i = 0; i < 32; ++i) acc[i] = 0;

        #pragma unroll 8
        for (int kw = 0; kw < 64; ++kw) {
            int4 a  = *reinterpret_cast<const int4*>(Z + (kw << 6) + (ty << 2));
            int4 b0 = *reinterpret_cast<const int4*>(Bp + (kw << 7) + (tx << 3));
            int4 b1 = *reinterpret_cast<const int4*>(Bp + (kw << 7) + (tx << 3) + 4);
            const int aa[4] = {a.x, a.y, a.z, a.w};
            const int bb[8] = {b0.x, b0.y, b0.z, b0.w, b1.x, b1.y, b1.z, b1.w};
            #pragma unroll
            for (int pi = 0; pi < 4; ++pi)
                #pragma unroll
                for (int cj = 0; cj < 8; ++cj)
                    acc[pi * 8 + cj] = __dp4a(aa[pi], bb[cj], acc[pi * 8 + cj]);
        }

        // epilogue: d = sume_j - 2*sz_p*se_j*acc ; dump bf16-packed scores
        const int jc = ci << 7;
        float q8[8], se8[8];
        #pragma unroll
        for (int cj = 0; cj < 8; ++cj) {
            const int j = jc + (tx << 3) + cj;
            se8[cj] = __ldg(&g_sume[j]);
            q8[cj]  = -2.f * __ldg(&g_se[j]);
        }
        #pragma unroll
        for (int pi = 0; pi < 4; ++pi) {
            const int n = blk * 64 + (ty << 2) + pi;
            float d0 = fmaf((float)acc[pi * 8 + 0] * q8[0], szp[pi], se8[0]);
            float d1 = fmaf((float)acc[pi * 8 + 1] * q8[1], szp[pi], se8[1]);
            float d2 = fmaf((float)acc[pi * 8 + 2] * q8[2], szp[pi], se8[2]);
            float d3 = fmaf((float)acc[pi * 8 + 3] * q8[3], szp[pi], se8[3]);
            float d4 = fmaf((float)acc[pi * 8 + 4] * q8[4], szp[pi], se8[4]);
            float d5 = fmaf((float)acc[pi * 8 + 5] * q8[5], szp[pi], se8[5]);
            float d6 = fmaf((float)acc[pi * 8 + 6] * q8[6], szp[pi], se8[6]);
            float d7 = fmaf((float)acc[pi * 8 + 7] * q8[7], szp[pi], se8[7]);
            uint4 v;
            v.x = pkbf(d0, d1); v.y = pkbf(d2, d3);
            v.z = pkbf(d4, d5); v.w = pkbf(d6, d7);
            g_db[(size_t)n * 256 + (ci << 4) + tx] = v;
        }

        asm volatile("cp.async.wait_group 0;" ::: "memory");
        __syncthreads();
    }
}

// ---------------------------------------------------------------------------
// collect: one warp per pixel; min computed FROM THE DUMPED VALUES themselves
// (self-consistent thresholding), then tight-window candidate selection.
// ---------------------------------------------------------------------------
__global__ void __launch_bounds__(256) collect_kernel() {
    __shared__ int scnt[8];
    __shared__ int scand[8][CAP];
    const int w = threadIdx.x >> 5, lane = threadIdx.x & 31;
    const int n = blockIdx.x * 8 + w;    // 8192 blocks

    if (lane == 0) scnt[w] = 0;
    __syncwarp();

    const uint4* dp = g_db + (size_t)n * 256;
    uint4 v[8];
    float mn = __int_as_float(0x7f800000);
    #pragma unroll
    for (int i = 0; i < 8; ++i) {
        v[i] = dp[i * 32 + lane];
        mn = fminf(mn, fminf(fminf(lo_bf(v[i].x), hi_bf(v[i].x)),
                             fminf(lo_bf(v[i].y), hi_bf(v[i].y))));
        mn = fminf(mn, fminf(fminf(lo_bf(v[i].z), hi_bf(v[i].z)),
                             fminf(lo_bf(v[i].w), hi_bf(v[i].w))));
    }
    #pragma unroll
    for (int off = 16; off; off >>= 1)
        mn = fminf(mn, __shfl_xor_sync(0xffffffffu, mn, off));

    const float thr = mn + g_eps[n];
    #pragma unroll
    for (int i = 0; i < 8; ++i) {
        const int j0 = (i * 32 + lane) * 8;
        if (lo_bf(v[i].x) <= thr) { int ix = atomicAdd(&scnt[w], 1); if (ix < CAP) scand[w][ix] = j0; }
        if (hi_bf(v[i].x) <= thr) { int ix = atomicAdd(&scnt[w], 1); if (ix < CAP) scand[w][ix] = j0 + 1; }
        if (lo_bf(v[i].y) <= thr) { int ix = atomicAdd(&scnt[w], 1); if (ix < CAP) scand[w][ix] = j0 + 2; }
        if (hi_bf(v[i].y) <= thr) { int ix = atomicAdd(&scnt[w], 1); if (ix < CAP) scand[w][ix] = j0 + 3; }
        if (lo_bf(v[i].z) <= thr) { int ix = atomicAdd(&scnt[w], 1); if (ix < CAP) scand[w][ix] = j0 + 4; }
        if (hi_bf(v[i].z) <= thr) { int ix = atomicAdd(&scnt[w], 1); if (ix < CAP) scand[w][ix] = j0 + 5; }
        if (lo_bf(v[i].w) <= thr) { int ix = atomicAdd(&scnt[w], 1); if (ix < CAP) scand[w][ix] = j0 + 6; }
        if (hi_bf(v[i].w) <= thr) { int ix = atomicAdd(&scnt[w], 1); if (ix < CAP) scand[w][ix] = j0 + 7; }
    }
    __syncwarp();
    if (lane == 0) g_cnt[n] = scnt[w];
    const int c = min(scnt[w], CAP);
    if (lane < c) g_cand[(size_t)n * CAP + lane] = scand[w][lane];
}

// ---------------------------------------------------------------------------
// refine: exact reference arithmetic on candidates -> g_idx
// ---------------------------------------------------------------------------
__device__ __forceinline__ void dot8(const float* __restrict__ z,
                                     const float* __restrict__ emb,
                                     size_t zbase, const int* ids,
                                     float* m, float& sz, bool do_sz) {
    #pragma unroll
    for (int i = 0; i < 8; ++i) m[i] = 0.f;
    for (int kc = 0; kc < 4; ++kc) {
        float zc[64];
        #pragma unroll
        for (int i = 0; i < 64; ++i)
            zc[i] = __ldg(&z[zbase + ((size_t)(kc * 64 + i) << 10)]);
        if (do_sz)
            #pragma unroll
            for (int i = 0; i < 64; ++i)
                sz = __fadd_rn(sz, __fmul_rn(zc[i], zc[i]));
        #pragma unroll
        for (int cd = 0; cd < 8; ++cd) {
            const float4* ep = reinterpret_cast<const float4*>(
                emb + (size_t)ids[cd] * DD + kc * 64);
            float mm = m[cd];
            #pragma unroll
            for (int q = 0; q < 16; ++q) {
                float4 e = __ldg(&ep[q]);
                mm = fmaf(zc[q * 4 + 0], e.x, mm);
                mm = fmaf(zc[q * 4 + 1], e.y, mm);
                mm = fmaf(zc[q * 4 + 2], e.z, mm);
                mm = fmaf(zc[q * 4 + 3], e.w, mm);
            }
            m[cd] = mm;
        }
    }
}

__global__ void __launch_bounds__(256) refine_kernel(const float* __restrict__ z,
                                                     const float* __restrict__ emb) {
    const int n = blockIdx.x * 256 + threadIdx.x;
    const int b = n >> 10, pix = n & 1023;
    const size_t zbase = ((size_t)b << 18) + pix;
    const int cnt = g_cnt[n];
    float best = __int_as_float(0x7f800000);
    int   bi = 0x7fffffff;
    float sz = 0.f;
    float m[8];
    int ids[8];

    if (cnt <= CAP) {
        for (int g0 = 0; g0 < cnt; g0 += 8) {
            #pragma unroll
            for (int i = 0; i < 8; ++i) {
                int q = g0 + i; if (q >= cnt) q = cnt - 1;
                ids[i] = g_cand[(size_t)n * CAP + q];
            }
            dot8(z, emb, zbase, ids, m, sz, g0 == 0);
            #pragma unroll
            for (int cd = 0; cd < 8; ++cd) {
                if (g0 + cd < cnt) {
                    int j = ids[cd];
                    float d = fmaf(m[cd], -2.f, __fadd_rn(sz, __ldg(&g_sume[j])));
                    if (d < best || (d == best && j < bi)) { best = d; bi = j; }
                }
            }
        }
    } else {
        for (int g0 = 0; g0 < KK; g0 += 8) {
            #pragma unroll
            for (int i = 0; i < 8; ++i) ids[i] = g0 + i;
            dot8(z, emb, zbase, ids, m, sz, g0 == 0);
            #pragma unroll
            for (int cd = 0; cd < 8; ++cd) {
                int j = g0 + cd;
                float d = fmaf(m[cd], -2.f, __fadd_rn(sz, __ldg(&g_sume[j])));
                if (d < best || (d == best && j < bi)) { best = d; bi = j; }
            }
        }
    }
    g_idx[n] = bi;
}

// ---------------------------------------------------------------------------
// quant: R1 version (measured 78us): gather + straight-through + loss
// ---------------------------------------------------------------------------
__global__ void __launch_bounds__(256)
quant_kernel(const float* __restrict__ z, const float* __restrict__ emb,
             float* __restrict__ out) {
    const size_t i = ((size_t)blockIdx.x * 256 + threadIdx.x) * 4;
    const int c = (int)((i >> 10) & 255);
    const int n = (int)(((i >> 18) << 10) | (i & 1023));

    int4   id4 = *reinterpret_cast<const int4*>(&g_idx[n]);
    float4 zp  = *reinterpret_cast<const float4*>(&z[i]);

    float e0 = __ldg(&emb[(size_t)id4.x * DD + c]);
    float e1 = __ldg(&emb[(size_t)id4.y * DD + c]);
    float e2 = __ldg(&emb[(size_t)id4.z * DD + c]);
    float e3 = __ldg(&emb[(size_t)id4.w * DD + c]);

    float t0 = __fsub_rn(e0, zp.x);
    float t1 = __fsub_rn(e1, zp.y);
    float t2 = __fsub_rn(e2, zp.z);
    float t3 = __fsub_rn(e3, zp.w);

    float4 o;
    o.x = __fadd_rn(zp.x, t0);
    o.y = __fadd_rn(zp.y, t1);
    o.z = __fadd_rn(zp.z, t2);
    o.w = __fadd_rn(zp.w, t3);
    *reinterpret_cast<float4*>(&out[i]) = o;

    double s = (double)__fmul_rn(t0, t0) + (double)__fmul_rn(t1, t1)
             + (double)__fmul_rn(t2, t2) + (double)__fmul_rn(t3, t3);

    #pragma unroll
    for (int off = 16; off; off >>= 1)
        s += __shfl_down_sync(0xffffffffu, s, off);
    __shared__ double ws[8];
    const int warp = threadIdx.x >> 5, lane = threadIdx.x & 31;
    if (lane == 0) ws[warp] = s;
    __syncthreads();
    if (threadIdx.x == 0) {
        double t = 0.0;
        #pragma unroll
        for (int w = 0; w < 8; ++w) t += ws[w];
        atomicAdd(&g_loss, t);
    }
}

// ---------------------------------------------------------------------------
__global__ void write_extras_kernel(float* __restrict__ out, int out_size) {
    const int t = blockIdx.x * 256 + threadIdx.x;
    if (out_size == NN) { if (t < NN) out[t] = (float)g_idx[t]; return; }
    const int rem = out_size - ZQ;
    if (rem >= NN && t < NN) out[ZQ + t] = (float)g_idx[t];
    if (rem >= NN + 1 && t == 0) {
        float m = (float)(g_loss * (1.0 / 16777216.0));
        out[ZQ + NN] = __fadd_rn(m, __fmul_rn(0.25f, m));
    }
    if (rem >= 2 * NN + 1 && t < NN) out[ZQ + NN + 1 + t] = (float)g_idx[t];
}

// ---------------------------------------------------------------------------
extern "C" void kernel_launch(void* const* d_in, const int* in_sizes, int n_in,
                              void* d_out, int out_size) {
    const float* z;
    const float* emb;
    if (in_sizes[0] == ZQ) { z = (const float*)d_in[0]; emb = (const float*)d_in[1]; }
    else                   { z = (const float*)d_in[1]; emb = (const float*)d_in[0]; }
    float* out = (float*)d_out;

    cudaFuncSetAttribute(assign_dp4a,
                         cudaFuncAttributeMaxDynamicSharedMemorySize, ASMEM);

    init_kernel<<<1, 1>>>();
    prep_e8<<<8, 256>>>(emb);
    assign_dp4a<<<1024, 256, ASMEM>>>(z);
    collect_kernel<<<NN / 8, 256>>>();
    refine_kernel<<<256, 256>>>(z, emb);
    if (out_size >= ZQ)
        quant_kernel<<<(NN * DD) / (256 * 4), 256>>>(z, emb, out);
    if (out_size > ZQ || out_size == NN)
        write_extras_kernel<<<NN / 256, 256>>>(out, out_size);
}

// round 16
// speedup vs baseline: 2.4881x; 1.0342x over previous
#include <cuda_runtime.h>
#include <cstdint>

#define NN 65536
#define DD 256
#define KK 2048
#define ZQ (NN*DD)
#define CAP 32

// ---------------------------------------------------------------------------
// device scratch
// ---------------------------------------------------------------------------
__device__ uint4    g_e8[16 * 2048];        // 512KB: [chunk 16][kw 64][code 128] int8x4
__device__ float    g_se[KK];               // per-code int8 scale
__device__ float    g_sume[KK];             // exact sequential sum(e^2)
__device__ float    g_SEmax;                // max_j sum|e_j| (with slack)
__device__ float    g_SEscale;              // max_j s_e (with slack)
__device__ uint4    g_db[(size_t)NN * 256]; // 256MB bf16 score dump (8 scores/uint4)
__device__ int      g_cand[NN * CAP];
__device__ int      g_cnt[NN];
__device__ int      g_idx[NN];
__device__ double   g_loss;

// ---------------------------------------------------------------------------
// helpers
// ---------------------------------------------------------------------------
__device__ __forceinline__ void cpasync16(void* sdst, const void* gsrc) {
    unsigned s = (unsigned)__cvta_generic_to_shared(sdst);
    asm volatile("cp.async.cg.shared.global [%0], [%1], 16;" :: "r"(s), "l"(gsrc));
}
__device__ __forceinline__ void atomicMaxF(float* addr, float v) {
    atomicMax(reinterpret_cast<int*>(addr), __float_as_int(v));  // v >= 0
}
// bf16 pack/unpack via integer ops (round-to-nearest-even), no half intrinsics
__device__ __forceinline__ uint32_t pkbf(float a, float b) {
    uint32_t ua = __float_as_uint(a);
    ua = (ua + 0x7fffu + ((ua >> 16) & 1u)) >> 16;
    uint32_t ub = __float_as_uint(b);
    ub = (ub + 0x7fffu + ((ub >> 16) & 1u)) >> 16;
    return ua | (ub << 16);
}
__device__ __forceinline__ float lo_bf(uint32_t v) { return __uint_as_float(v << 16); }
__device__ __forceinline__ float hi_bf(uint32_t v) { return __uint_as_float(v & 0xffff0000u); }

// ---------------------------------------------------------------------------
__global__ void init_kernel() { g_SEmax = 0.f; g_SEscale = 0.f; g_loss = 0.0; }

// ---------------------------------------------------------------------------
// prep_e8: per-code int8 quant + exact sume + bound scalars (proven)
// ---------------------------------------------------------------------------
__global__ void prep_e8(const float* __restrict__ emb) {
    const int j = blockIdx.x * 256 + threadIdx.x;   // 2048
    const float* e = emb + (size_t)j * DD;

    float s = 0.f;
    for (int c = 0; c < DD; ++c) {
        float v = e[c];
        s = __fadd_rn(s, __fmul_rn(v, v));
    }
    g_sume[j] = s;

    float mx = 0.f, sa = 0.f;
    for (int c = 0; c < DD; ++c) {
        float a = fabsf(e[c]);
        mx = fmaxf(mx, a);
        sa += a;
    }
    const float mxs = fmaxf(mx, 1e-30f);
    const float se  = mxs / 127.f;
    const float inv = 127.f / mxs;
    g_se[j] = se;
    atomicMaxF(&g_SEmax, sa * 1.0005f);
    atomicMaxF(&g_SEscale, se * 1.0005f);

    const int chunk = j >> 7, code = j & 127;
    uint32_t* dst = reinterpret_cast<uint32_t*>(g_e8) + (size_t)chunk * 8192 + code;
    for (int kw = 0; kw < 64; ++kw) {
        int q0 = max(-127, min(127, __float2int_rn(e[kw * 4 + 0] * inv)));
        int q1 = max(-127, min(127, __float2int_rn(e[kw * 4 + 1] * inv)));
        int q2 = max(-127, min(127, __float2int_rn(e[kw * 4 + 2] * inv)));
        int q3 = max(-127, min(127, __float2int_rn(e[kw * 4 + 3] * inv)));
        dst[kw * 128] = (uint32_t)(q0 & 0xFF) | ((uint32_t)(q1 & 0xFF) << 8)
                      | ((uint32_t)(q2 & 0xFF) << 16) | ((uint32_t)(q3 & 0xFF) << 24);
    }
}

// ---------------------------------------------------------------------------
// assign_dp4a: 64 pixels x 2048 codes per CTA (grid = 1024); z quantized
// in-kernel to int8 (per-pixel scale); e chunks double-buffered; dp4a GEMM;
// scores dumped bf16 to g_db; SELF-CONSISTENT fused collect at the tail
// (min computed from the re-read dumped bf16 values — R13's proven logic).
// smem: Z8 16K | E8 2x32K | m2 1K | sa2 1K | sps 256 | eps 256 |
//       cnt 256 | cand 8192   = 92928
// ---------------------------------------------------------------------------
#define OFF_Z    0
#define OFF_E    16384
#define OFF_M2   81920
#define OFF_SA2  82944
#define OFF_SPS  83968
#define OFF_EPS  84224
#define OFF_CNT  84480
#define OFF_CAND 84736
#define ASMEM    92928

__global__ void __launch_bounds__(256, 2) assign_dp4a(const float* __restrict__ z) {
    extern __shared__ char sm[];
    uint32_t* Z    = reinterpret_cast<uint32_t*>(sm + OFF_Z);
    uint32_t* E    = reinterpret_cast<uint32_t*>(sm + OFF_E);
    float*    m2   = reinterpret_cast<float*>(sm + OFF_M2);
    float*    sa2  = reinterpret_cast<float*>(sm + OFF_SA2);
    float*    sps  = reinterpret_cast<float*>(sm + OFF_SPS);
    float*    epss = reinterpret_cast<float*>(sm + OFF_EPS);
    int*      cnt  = reinterpret_cast<int*>(sm + OFF_CNT);
    int*      cand = reinterpret_cast<int*>(sm + OFF_CAND);

    const int tid = threadIdx.x;
    const int tx = tid & 15, ty = tid >> 4;   // tx: 8 codes, ty: 4 pixels
    const int w = tid >> 5, lane = tid & 31;
    const int blk = blockIdx.x;               // 1024 (64 pixels each)
    const int b = blk >> 4, px0 = (blk & 15) << 6;
    const float* zb = z + ((size_t)b << 18) + px0;
    const int px = tid & 63, seg = tid >> 6;  // 4 segs x 64 dims

    // E chunk 0 prefetch (overlaps the z-quant pass)
    {
        const char* es = reinterpret_cast<const char*>(g_e8);
        #pragma unroll
        for (int i = 0; i < 8; ++i) {
            const int t = tid + i * 256;
            cpasync16(sm + OFF_E + t * 16, es + (size_t)t * 16);
        }
    }
    asm volatile("cp.async.commit_group;" ::: "memory");

    if (tid < 64) cnt[tid] = 0;

    // ---- pass 1: per-pixel maxabs + sum|z| ----
    {
        float mx = 0.f, sa = 0.f;
        #pragma unroll 8
        for (int i = 0; i < 64; ++i) {
            float v = __ldg(&zb[((size_t)(seg * 64 + i) << 10) + px]);
            float a = fabsf(v);
            mx = fmaxf(mx, a);
            sa += a;
        }
        m2[tid] = mx; sa2[tid] = sa;
    }
    __syncthreads();
    if (tid < 64) {
        float mx = fmaxf(fmaxf(m2[tid], m2[tid + 64]),
                         fmaxf(m2[tid + 128], m2[tid + 192]));
        float sa = sa2[tid] + sa2[tid + 64] + sa2[tid + 128] + sa2[tid + 192];
        const float mxs = fmaxf(mx, 1e-30f);
        const float sz = mxs / 127.f;
        sps[tid] = sz;
        m2[tid]  = 127.f / mxs;   // reuse as inv
        // window = 2B + fp32 slack + bf16 dump slack (2 * 1.2e-4)
        const float B = 0.5f * sz * g_SEmax
                      + 0.5f * g_SEscale * (sa * 1.0005f + 128.f * sz);
        epss[tid] = 2.f * B + 1e-4f + 2.4e-4f;
    }
    __syncthreads();

    // ---- pass 2: quantize z -> Z8 [kw][px] ----
    {
        const float inv = m2[px];
        for (int kw = seg * 16; kw < seg * 16 + 16; ++kw) {
            const int c0 = kw * 4;
            int q0 = max(-127, min(127, __float2int_rn(__ldg(&zb[((size_t)(c0 + 0) << 10) + px]) * inv)));
            int q1 = max(-127, min(127, __float2int_rn(__ldg(&zb[((size_t)(c0 + 1) << 10) + px]) * inv)));
            int q2 = max(-127, min(127, __float2int_rn(__ldg(&zb[((size_t)(c0 + 2) << 10) + px]) * inv)));
            int q3 = max(-127, min(127, __float2int_rn(__ldg(&zb[((size_t)(c0 + 3) << 10) + px]) * inv)));
            Z[(kw << 6) + px] = (uint32_t)(q0 & 0xFF) | ((uint32_t)(q1 & 0xFF) << 8)
                              | ((uint32_t)(q2 & 0xFF) << 16) | ((uint32_t)(q3 & 0xFF) << 24);
        }
    }
    asm volatile("cp.async.wait_group 0;" ::: "memory");
    __syncthreads();

    float szp[4];
    #pragma unroll
    for (int pi = 0; pi < 4; ++pi) szp[pi] = sps[(ty << 2) + pi];

    for (int ci = 0; ci < 16; ++ci) {
        if (ci + 1 < 16) {
            const char* es = reinterpret_cast<const char*>(g_e8) + (size_t)(ci + 1) * 32768;
            char* dst = sm + OFF_E + ((ci + 1) & 1) * 32768;
            #pragma unroll
            for (int i = 0; i < 8; ++i) {
                const int t = tid + i * 256;
                cpasync16(dst + t * 16, es + (size_t)t * 16);
            }
        }
        asm volatile("cp.async.commit_group;" ::: "memory");

        const uint32_t* Bp = E + (ci & 1) * 8192;
        int acc[32];
        #pragma unroll
        for (int i = 0; i < 32; ++i) acc[i] = 0;

        #pragma unroll 8
        for (int kw = 0; kw < 64; ++kw) {
            int4 a  = *reinterpret_cast<const int4*>(Z + (kw << 6) + (ty << 2));
            int4 b0 = *reinterpret_cast<const int4*>(Bp + (kw << 7) + (tx << 3));
            int4 b1 = *reinterpret_cast<const int4*>(Bp + (kw << 7) + (tx << 3) + 4);
            #pragma unroll
            for (int cj = 0; cj < 4; ++cj) {
                const int bv0 = (&b0.x)[cj];
                const int bv1 = (&b1.x)[cj];
                #pragma unroll
                for (int pi = 0; pi < 4; ++pi) {
                    acc[pi * 8 + cj]     = __dp4a((&a.x)[pi], bv0, acc[pi * 8 + cj]);
                    acc[pi * 8 + 4 + cj] = __dp4a((&a.x)[pi], bv1, acc[pi * 8 + 4 + cj]);
                }
            }
        }

        // epilogue: d = sume_j - 2*sz_p*se_j*acc ; dump bf16-packed scores
        const int jc = ci << 7;
        float q8[8], se8[8];
        #pragma unroll
        for (int cj = 0; cj < 8; ++cj) {
            const int j = jc + (tx << 3) + cj;
            se8[cj] = __ldg(&g_sume[j]);
            q8[cj]  = -2.f * __ldg(&g_se[j]);
        }
        #pragma unroll
        for (int pi = 0; pi < 4; ++pi) {
            const int n = blk * 64 + (ty << 2) + pi;
            float d0 = fmaf((float)acc[pi * 8 + 0] * q8[0], szp[pi], se8[0]);
            float d1 = fmaf((float)acc[pi * 8 + 1] * q8[1], szp[pi], se8[1]);
            float d2 = fmaf((float)acc[pi * 8 + 2] * q8[2], szp[pi], se8[2]);
            float d3 = fmaf((float)acc[pi * 8 + 3] * q8[3], szp[pi], se8[3]);
            float d4 = fmaf((float)acc[pi * 8 + 4] * q8[4], szp[pi], se8[4]);
            float d5 = fmaf((float)acc[pi * 8 + 5] * q8[5], szp[pi], se8[5]);
            float d6 = fmaf((float)acc[pi * 8 + 6] * q8[6], szp[pi], se8[6]);
            float d7 = fmaf((float)acc[pi * 8 + 7] * q8[7], szp[pi], se8[7]);
            uint4 v;
            v.x = pkbf(d0, d1); v.y = pkbf(d2, d3);
            v.z = pkbf(d4, d5); v.w = pkbf(d6, d7);
            g_db[(size_t)n * 256 + (ci << 4) + tx] = v;
        }

        asm volatile("cp.async.wait_group 0;" ::: "memory");
        __syncthreads();
    }
    // all dump stores visible block-wide past this barrier (done above)

    // ---- fused collect (R13 logic): warp w owns pixels w*8 .. w*8+7 ----
    for (int pp = 0; pp < 8; ++pp) {
        const int p = (w << 3) + pp;
        const uint4* dp = g_db + (size_t)(blk * 64 + p) * 256;
        uint4 v[8];
        float mn = __int_as_float(0x7f800000);
        #pragma unroll
        for (int i = 0; i < 8; ++i) {
            v[i] = dp[i * 32 + lane];
            mn = fminf(mn, fminf(fminf(lo_bf(v[i].x), hi_bf(v[i].x)),
                                 fminf(lo_bf(v[i].y), hi_bf(v[i].y))));
            mn = fminf(mn, fminf(fminf(lo_bf(v[i].z), hi_bf(v[i].z)),
                                 fminf(lo_bf(v[i].w), hi_bf(v[i].w))));
        }
        #pragma unroll
        for (int off = 16; off; off >>= 1)
            mn = fminf(mn, __shfl_xor_sync(0xffffffffu, mn, off));

        const float thr = mn + epss[p];
        #pragma unroll
        for (int i = 0; i < 8; ++i) {
            const int j0 = (i * 32 + lane) * 8;
            if (lo_bf(v[i].x) <= thr) { int ix = atomicAdd(&cnt[p], 1); if (ix < CAP) cand[p * CAP + ix] = j0; }
            if (hi_bf(v[i].x) <= thr) { int ix = atomicAdd(&cnt[p], 1); if (ix < CAP) cand[p * CAP + ix] = j0 + 1; }
            if (lo_bf(v[i].y) <= thr) { int ix = atomicAdd(&cnt[p], 1); if (ix < CAP) cand[p * CAP + ix] = j0 + 2; }
            if (hi_bf(v[i].y) <= thr) { int ix = atomicAdd(&cnt[p], 1); if (ix < CAP) cand[p * CAP + ix] = j0 + 3; }
            if (lo_bf(v[i].z) <= thr) { int ix = atomicAdd(&cnt[p], 1); if (ix < CAP) cand[p * CAP + ix] = j0 + 4; }
            if (hi_bf(v[i].z) <= thr) { int ix = atomicAdd(&cnt[p], 1); if (ix < CAP) cand[p * CAP + ix] = j0 + 5; }
            if (lo_bf(v[i].w) <= thr) { int ix = atomicAdd(&cnt[p], 1); if (ix < CAP) cand[p * CAP + ix] = j0 + 6; }
            if (hi_bf(v[i].w) <= thr) { int ix = atomicAdd(&cnt[p], 1); if (ix < CAP) cand[p * CAP + ix] = j0 + 7; }
        }
    }
    __syncthreads();

    if (tid < 64) {
        const int n = blk * 64 + tid;
        int c = cnt[tid];
        g_cnt[n] = c;
        if (c > CAP) c = CAP;
        for (int i = 0; i < c; ++i) g_cand[(size_t)n * CAP + i] = cand[tid * CAP + i];
    }
}

// ---------------------------------------------------------------------------
// refine: exact reference arithmetic on candidates -> g_idx
// ---------------------------------------------------------------------------
__device__ __forceinline__ void dot8(const float* __restrict__ z,
                                     const float* __restrict__ emb,
                                     size_t zbase, const int* ids,
                                     float* m, float& sz, bool do_sz) {
    #pragma unroll
    for (int i = 0; i < 8; ++i) m[i] = 0.f;
    for (int kc = 0; kc < 4; ++kc) {
        float zc[64];
        #pragma unroll
        for (int i = 0; i < 64; ++i)
            zc[i] = __ldg(&z[zbase + ((size_t)(kc * 64 + i) << 10)]);
        if (do_sz)
            #pragma unroll
            for (int i = 0; i < 64; ++i)
                sz = __fadd_rn(sz, __fmul_rn(zc[i], zc[i]));
        #pragma unroll
        for (int cd = 0; cd < 8; ++cd) {
            const float4* ep = reinterpret_cast<const float4*>(
                emb + (size_t)ids[cd] * DD + kc * 64);
            float mm = m[cd];
            #pragma unroll
            for (int q = 0; q < 16; ++q) {
                float4 e = __ldg(&ep[q]);
                mm = fmaf(zc[q * 4 + 0], e.x, mm);
                mm = fmaf(zc[q * 4 + 1], e.y, mm);
                mm = fmaf(zc[q * 4 + 2], e.z, mm);
                mm = fmaf(zc[q * 4 + 3], e.w, mm);
            }
            m[cd] = mm;
        }
    }
}

__global__ void __launch_bounds__(256) refine_kernel(const float* __restrict__ z,
                                                     const float* __restrict__ emb) {
    const int n = blockIdx.x * 256 + threadIdx.x;
    const int b = n >> 10, pix = n & 1023;
    const size_t zbase = ((size_t)b << 18) + pix;
    const int cnt = g_cnt[n];
    float best = __int_as_float(0x7f800000);
    int   bi = 0x7fffffff;
    float sz = 0.f;
    float m[8];
    int ids[8];

    if (cnt <= CAP) {
        for (int g0 = 0; g0 < cnt; g0 += 8) {
            #pragma unroll
            for (int i = 0; i < 8; ++i) {
                int q = g0 + i; if (q >= cnt) q = cnt - 1;
                ids[i] = g_cand[(size_t)n * CAP + q];
            }
            dot8(z, emb, zbase, ids, m, sz, g0 == 0);
            #pragma unroll
            for (int cd = 0; cd < 8; ++cd) {
                if (g0 + cd < cnt) {
                    int j = ids[cd];
                    float d = fmaf(m[cd], -2.f, __fadd_rn(sz, __ldg(&g_sume[j])));
                    if (d < best || (d == best && j < bi)) { best = d; bi = j; }
                }
            }
        }
    } else {
        for (int g0 = 0; g0 < KK; g0 += 8) {
            #pragma unroll
            for (int i = 0; i < 8; ++i) ids[i] = g0 + i;
            dot8(z, emb, zbase, ids, m, sz, g0 == 0);
            #pragma unroll
            for (int cd = 0; cd < 8; ++cd) {
                int j = g0 + cd;
                float d = fmaf(m[cd], -2.f, __fadd_rn(sz, __ldg(&g_sume[j])));
                if (d < best || (d == best && j < bi)) { best = d; bi = j; }
            }
        }
    }
    g_idx[n] = bi;
}

// ---------------------------------------------------------------------------
// quant: tiled 64 pixels x 256 dims; emb rows staged in smem (coalesced);
// straight-through + loss, exact reference arithmetic per element.
// dynamic smem: es 64*257*4 = 65792 | ids 256 | ws 64  -> 66112
// ---------------------------------------------------------------------------
#define QSMEM 66112

__global__ void __launch_bounds__(256) quant_kernel(const float* __restrict__ z,
                                                    const float* __restrict__ emb,
                                                    float* __restrict__ out) {
    extern __shared__ char qsm[];
    float*  es  = reinterpret_cast<float*>(qsm);            // [64][257]
    int*    ids = reinterpret_cast<int*>(qsm + 65792);      // [64]
    double* ws  = reinterpret_cast<double*>(qsm + 66048);   // [8]

    const int tid = threadIdx.x, w = tid >> 5, lane = tid & 31;
    const int n0 = blockIdx.x * 64;                         // 1024 blocks
    const int b = n0 >> 10, pl = n0 & 1023;

    if (tid < 64) ids[tid] = g_idx[n0 + tid];
    __syncthreads();
    #pragma unroll 4
    for (int r = 0; r < 64; ++r)
        es[r * 257 + tid] = __ldg(&emb[(size_t)ids[r] * DD + tid]);
    __syncthreads();

    const int px = tid & 63, cg = tid >> 6;                 // 4 dim-groups
    const size_t base = ((size_t)b << 18) + pl + px;
    double ls = 0.0;
    #pragma unroll 4
    for (int i = 0; i < 64; ++i) {
        const int c = cg * 64 + i;
        float zp = z[base + ((size_t)c << 10)];
        float e  = es[px * 257 + c];
        float t  = __fsub_rn(e, zp);
        out[base + ((size_t)c << 10)] = __fadd_rn(zp, t);
        ls += (double)__fmul_rn(t, t);
    }
    #pragma unroll
    for (int off = 16; off; off >>= 1)
        ls += __shfl_down_sync(0xffffffffu, ls, off);
    if (lane == 0) ws[w] = ls;
    __syncthreads();
    if (tid == 0) {
        double t = 0.0;
        #pragma unroll
        for (int i = 0; i < 8; ++i) t += ws[i];
        atomicAdd(&g_loss, t);
    }
}

// ---------------------------------------------------------------------------
__global__ void write_extras_kernel(float* __restrict__ out, int out_size) {
    const int t = blockIdx.x * 256 + threadIdx.x;
    if (out_size == NN) { if (t < NN) out[t] = (float)g_idx[t]; return; }
    const int rem = out_size - ZQ;
    if (rem >= NN && t < NN) out[ZQ + t] = (float)g_idx[t];
    if (rem >= NN + 1 && t == 0) {
        float m = (float)(g_loss * (1.0 / 16777216.0));
        out[ZQ + NN] = __fadd_rn(m, __fmul_rn(0.25f, m));
    }
    if (rem >= 2 * NN + 1 && t < NN) out[ZQ + NN + 1 + t] = (float)g_idx[t];
}

// ---------------------------------------------------------------------------
extern "C" void kernel_launch(void* const* d_in, const int* in_sizes, int n_in,
                              void* d_out, int out_size) {
    const float* z;
    const float* emb;
    if (in_sizes[0] == ZQ) { z = (const float*)d_in[0]; emb = (const float*)d_in[1]; }
    else                   { z = (const float*)d_in[1]; emb = (const float*)d_in[0]; }
    float* out = (float*)d_out;

    cudaFuncSetAttribute(assign_dp4a,
                         cudaFuncAttributeMaxDynamicSharedMemorySize, ASMEM);
    cudaFuncSetAttribute(quant_kernel,
                         cudaFuncAttributeMaxDynamicSharedMemorySize, QSMEM);

    init_kernel<<<1, 1>>>();
    prep_e8<<<8, 256>>>(emb);
    assign_dp4a<<<1024, 256, ASMEM>>>(z);
    refine_kernel<<<256, 256>>>(z, emb);
    if (out_size >= ZQ)
        quant_kernel<<<NN / 64, 256, QSMEM>>>(z, emb, out);
    if (out_size > ZQ || out_size == NN)
        write_extras_kernel<<<NN / 256, 256>>>(out, out_size);
}